// round 1
// baseline (speedup 1.0000x reference)
#include <cuda_runtime.h>
#include <cuda_fp16.h>

typedef unsigned long long ull;

// ---------------- scratch (static device allocations; no cudaMalloc) ----------------
__device__ float  g_xw1[268435456];  // [T=512][B=1024][j=128][q=4] fp32  (1 GiB)
__device__ float  g_xw2[134217728];  // [T=512][B=1024][j=64][q=4]  fp32  (512 MiB)
__device__ __half g_hs1[67108864];   // [T=512][B=1024][128]        fp16  (128 MiB)

// ---------------- helpers ----------------
__device__ __forceinline__ ull pack2(float lo, float hi){
    ull r; asm("mov.b64 %0, {%1, %2};" : "=l"(r) : "f"(lo), "f"(hi)); return r;
}
__device__ __forceinline__ float2 unpack2(ull v){
    float2 f; asm("mov.b64 {%0, %1}, %2;" : "=f"(f.x), "=f"(f.y) : "l"(v)); return f;
}
__device__ __forceinline__ ull ffma2(ull a, ull b, ull c){
    ull d; asm("fma.rn.f32x2 %0, %1, %2, %3;" : "=l"(d) : "l"(a), "l"(b), "l"(c)); return d;
}
__device__ __forceinline__ float sigf(float x){ return 1.f / (1.f + __expf(-x)); }
__device__ __forceinline__ float tanh_f(float x){ return 1.f - 2.f / (__expf(2.f * x) + 1.f); }

// =====================================================================
// GEMM1: xw1[(t,b), c] = sum_e X[(b,t), e] * W1_ih[g(c), e] + b1_ih[g]+b1_hh[g]
// column c = j*4 + q, gate row g = q*128 + j   (PyTorch i,f,g,o order)
// Tile: 128 rows x 64 cols, K=100. f32x2 packed along columns.
// =====================================================================
__global__ void __launch_bounds__(256) gemm1_kernel(
    const float* __restrict__ X, const float* __restrict__ W,
    const float* __restrict__ bih, const float* __restrict__ bhh)
{
    extern __shared__ float sm[];
    float* sAT = sm;               // [100][132]  (transposed A, padded)
    float* sB  = sm + 100 * 132;   // [100][68]   (64 used, padded)
    const int tid = threadIdx.x;
    const int cb = blockIdx.x, rb = blockIdx.y;
    const size_t r0 = (size_t)rb * 128;

    const float* Ab = X + r0 * 100;             // rows r = b*512 + t are contiguous
    for (int idx = tid; idx < 12800; idx += 256){
        int i = idx / 100, e = idx - i * 100;
        sAT[e * 132 + i] = Ab[idx];
    }
    for (int idx = tid; idx < 6400; idx += 256){
        int gi = idx / 100, k = idx - gi * 100;  // coalesced along k
        int q = gi >> 4, jo = gi & 15;
        int g = q * 128 + cb * 16 + jo;
        int n = jo * 4 + q;
        sB[k * 68 + n] = W[g * 100 + k];
    }
    __syncthreads();

    const int ty = tid >> 4, tx = tid & 15;
    ull acc[8][2];
    #pragma unroll
    for (int r = 0; r < 8; r++){ acc[r][0] = 0ull; acc[r][1] = 0ull; }

    const float* ap0 = sAT + ty * 8;
    const float* bp0 = sB  + tx * 4;
    #pragma unroll 2
    for (int k = 0; k < 100; k++){
        float4 a0 = *(const float4*)(ap0 + k * 132);
        float4 a1 = *(const float4*)(ap0 + k * 132 + 4);
        ulonglong2 bv = *(const ulonglong2*)(bp0 + k * 68);
        ull ap;
        ap = pack2(a0.x, a0.x); acc[0][0]=ffma2(ap,bv.x,acc[0][0]); acc[0][1]=ffma2(ap,bv.y,acc[0][1]);
        ap = pack2(a0.y, a0.y); acc[1][0]=ffma2(ap,bv.x,acc[1][0]); acc[1][1]=ffma2(ap,bv.y,acc[1][1]);
        ap = pack2(a0.z, a0.z); acc[2][0]=ffma2(ap,bv.x,acc[2][0]); acc[2][1]=ffma2(ap,bv.y,acc[2][1]);
        ap = pack2(a0.w, a0.w); acc[3][0]=ffma2(ap,bv.x,acc[3][0]); acc[3][1]=ffma2(ap,bv.y,acc[3][1]);
        ap = pack2(a1.x, a1.x); acc[4][0]=ffma2(ap,bv.x,acc[4][0]); acc[4][1]=ffma2(ap,bv.y,acc[4][1]);
        ap = pack2(a1.y, a1.y); acc[5][0]=ffma2(ap,bv.x,acc[5][0]); acc[5][1]=ffma2(ap,bv.y,acc[5][1]);
        ap = pack2(a1.z, a1.z); acc[6][0]=ffma2(ap,bv.x,acc[6][0]); acc[6][1]=ffma2(ap,bv.y,acc[6][1]);
        ap = pack2(a1.w, a1.w); acc[7][0]=ffma2(ap,bv.x,acc[7][0]); acc[7][1]=ffma2(ap,bv.y,acc[7][1]);
    }

    const int cbase = cb * 64 + tx * 4;
    float bias[4];
    #pragma unroll
    for (int c = 0; c < 4; c++){
        int cc = cbase + c; int j = cc >> 2, q = cc & 3; int g = q * 128 + j;
        bias[c] = bih[g] + bhh[g];
    }
    #pragma unroll
    for (int r = 0; r < 8; r++){
        size_t row = r0 + ty * 8 + r;          // row = b*512 + t
        int bidx = (int)(row >> 9);
        int tidx = (int)(row & 511);
        size_t o = ((size_t)tidx * 1024 + bidx) * 512 + cbase;
        float2 p0 = unpack2(acc[r][0]); float2 p1 = unpack2(acc[r][1]);
        float4 v = make_float4(p0.x + bias[0], p0.y + bias[1], p1.x + bias[2], p1.y + bias[3]);
        *(float4*)(g_xw1 + o) = v;
    }
}

// =====================================================================
// GEMM2: xw2[(t,b), c] = sum_k hs1[(t,b), k] * W2_ih[g(c), k] + b2_ih[g]+b2_hh[g]
// column c = j*4 + q, g = q*64 + j.  K=128, A is fp16 (hs1).
// =====================================================================
__global__ void __launch_bounds__(256) gemm2_kernel(
    const float* __restrict__ W, const float* __restrict__ bih, const float* __restrict__ bhh)
{
    extern __shared__ float sm[];
    float* sAT = sm;               // [128][132]
    float* sB  = sm + 128 * 132;   // [128][68]
    const int tid = threadIdx.x;
    const int cb = blockIdx.x, rb = blockIdx.y;
    const size_t rr0 = (size_t)rb * 128;

    const __half2* Ah2 = (const __half2*)(g_hs1 + rr0 * 128);
    for (int idx = tid; idx < 8192; idx += 256){
        int i = idx >> 6, k2 = idx & 63;
        float2 f = __half22float2(Ah2[i * 64 + k2]);
        sAT[(2 * k2)     * 132 + i] = f.x;
        sAT[(2 * k2 + 1) * 132 + i] = f.y;
    }
    for (int idx = tid; idx < 8192; idx += 256){
        int gi = idx >> 7, k = idx & 127;      // coalesced along k
        int q = gi >> 4, jo = gi & 15;
        int g = q * 64 + cb * 16 + jo;
        int n = jo * 4 + q;
        sB[k * 68 + n] = W[g * 128 + k];
    }
    __syncthreads();

    const int ty = tid >> 4, tx = tid & 15;
    ull acc[8][2];
    #pragma unroll
    for (int r = 0; r < 8; r++){ acc[r][0] = 0ull; acc[r][1] = 0ull; }

    const float* ap0 = sAT + ty * 8;
    const float* bp0 = sB  + tx * 4;
    #pragma unroll 2
    for (int k = 0; k < 128; k++){
        float4 a0 = *(const float4*)(ap0 + k * 132);
        float4 a1 = *(const float4*)(ap0 + k * 132 + 4);
        ulonglong2 bv = *(const ulonglong2*)(bp0 + k * 68);
        ull ap;
        ap = pack2(a0.x, a0.x); acc[0][0]=ffma2(ap,bv.x,acc[0][0]); acc[0][1]=ffma2(ap,bv.y,acc[0][1]);
        ap = pack2(a0.y, a0.y); acc[1][0]=ffma2(ap,bv.x,acc[1][0]); acc[1][1]=ffma2(ap,bv.y,acc[1][1]);
        ap = pack2(a0.z, a0.z); acc[2][0]=ffma2(ap,bv.x,acc[2][0]); acc[2][1]=ffma2(ap,bv.y,acc[2][1]);
        ap = pack2(a0.w, a0.w); acc[3][0]=ffma2(ap,bv.x,acc[3][0]); acc[3][1]=ffma2(ap,bv.y,acc[3][1]);
        ap = pack2(a1.x, a1.x); acc[4][0]=ffma2(ap,bv.x,acc[4][0]); acc[4][1]=ffma2(ap,bv.y,acc[4][1]);
        ap = pack2(a1.y, a1.y); acc[5][0]=ffma2(ap,bv.x,acc[5][0]); acc[5][1]=ffma2(ap,bv.y,acc[5][1]);
        ap = pack2(a1.z, a1.z); acc[6][0]=ffma2(ap,bv.x,acc[6][0]); acc[6][1]=ffma2(ap,bv.y,acc[6][1]);
        ap = pack2(a1.w, a1.w); acc[7][0]=ffma2(ap,bv.x,acc[7][0]); acc[7][1]=ffma2(ap,bv.y,acc[7][1]);
    }

    const int cbase = cb * 64 + tx * 4;
    float bias[4];
    #pragma unroll
    for (int c = 0; c < 4; c++){
        int cc = cbase + c; int j = cc >> 2, q = cc & 3; int g = q * 64 + j;
        bias[c] = bih[g] + bhh[g];
    }
    #pragma unroll
    for (int r = 0; r < 8; r++){
        size_t rr = rr0 + ty * 8 + r;          // rr = t*1024 + b already
        size_t o = rr * 256 + cbase;
        float2 p0 = unpack2(acc[r][0]); float2 p1 = unpack2(acc[r][1]);
        float4 v = make_float4(p0.x + bias[0], p0.y + bias[1], p1.x + bias[2], p1.y + bias[3]);
        *(float4*)(g_xw2 + o) = v;
    }
}

// =====================================================================
// REC1: LSTM layer 1 recurrence. 128 CTAs x 8 batch rows, 256 threads.
// Thread = (unit j in 0..127, batch-half mh). Owns all 4 gates of unit j
// for 4 batch rows (2 f32x2 pairs). W1_hh fp16 in SMEM [k][j][q].
// =====================================================================
__global__ void __launch_bounds__(256) rec1_kernel(const float* __restrict__ Whh)
{
    extern __shared__ char smc[];
    __half* sW = (__half*)smc;                 // [128][128][4] = 128 KiB
    float*  sH = (float*)(smc + 131072);       // [k=128][m=8]  = 4 KiB
    const int tid = threadIdx.x;
    const int b0 = blockIdx.x * 8;

    for (int idx = tid; idx < 65536; idx += 256){
        int k = idx & 127;
        int j = (idx >> 7) & 127;
        int q = idx >> 14;
        sW[(k * 128 + j) * 4 + q] = __float2half(Whh[(q * 128 + j) * 128 + k]);
    }
    for (int i = tid; i < 1024; i += 256) sH[i] = 0.f;
    __syncthreads();

    const int j = tid & 127, mh = tid >> 7;
    float cst[4] = {0.f, 0.f, 0.f, 0.f};
    const uint2* wp  = (const uint2*)sW + j;   // [k][j] -> 4 fp16 gates
    const float* hp0 = sH + mh * 4;

    for (int t = 0; t < 512; t++){
        // prefetch xw1 for this step (consumed after the GEMM loop -> latency hidden)
        size_t base = ((size_t)t * 1024 + b0) * 512 + (size_t)j * 4;
        float4 xv[2][2];
        #pragma unroll
        for (int p = 0; p < 2; p++){
            int m0 = mh * 4 + p * 2;
            xv[p][0] = *(const float4*)(g_xw1 + base + (size_t)m0 * 512);
            xv[p][1] = *(const float4*)(g_xw1 + base + (size_t)(m0 + 1) * 512);
        }

        ull acc[4][2] = {{0ull,0ull},{0ull,0ull},{0ull,0ull},{0ull,0ull}};
        #pragma unroll 4
        for (int k = 0; k < 128; k++){
            uint2 wraw = wp[k * 128];
            float2 w01 = __half22float2(*(const __half2*)&wraw.x);
            float2 w23 = __half22float2(*(const __half2*)&wraw.y);
            ulonglong2 hv = *(const ulonglong2*)(hp0 + k * 8);
            ull W0 = pack2(w01.x, w01.x);
            ull W1 = pack2(w01.y, w01.y);
            ull W2 = pack2(w23.x, w23.x);
            ull W3 = pack2(w23.y, w23.y);
            acc[0][0]=ffma2(W0,hv.x,acc[0][0]); acc[0][1]=ffma2(W0,hv.y,acc[0][1]);
            acc[1][0]=ffma2(W1,hv.x,acc[1][0]); acc[1][1]=ffma2(W1,hv.y,acc[1][1]);
            acc[2][0]=ffma2(W2,hv.x,acc[2][0]); acc[2][1]=ffma2(W2,hv.y,acc[2][1]);
            acc[3][0]=ffma2(W3,hv.x,acc[3][0]); acc[3][1]=ffma2(W3,hv.y,acc[3][1]);
        }
        __syncthreads();   // all reads of old h done

        #pragma unroll
        for (int p = 0; p < 2; p++){
            float2 gi_ = unpack2(acc[0][p]);
            float2 gf_ = unpack2(acc[1][p]);
            float2 gg_ = unpack2(acc[2][p]);
            float2 go_ = unpack2(acc[3][p]);
            #pragma unroll
            for (int L = 0; L < 2; L++){
                const float4 x4 = xv[p][L];
                float ai = (L ? gi_.y : gi_.x) + x4.x;
                float af = (L ? gf_.y : gf_.x) + x4.y;
                float ag = (L ? gg_.y : gg_.x) + x4.z;
                float ao = (L ? go_.y : go_.x) + x4.w;
                float iv = sigf(ai), fv = sigf(af), gv = tanh_f(ag), ov = sigf(ao);
                int ci = p * 2 + L;
                float cn = fv * cst[ci] + iv * gv;
                cst[ci] = cn;
                float h = ov * tanh_f(cn);
                int m = mh * 4 + p * 2 + L;
                sH[j * 8 + m] = h;
                g_hs1[((size_t)t * 1024 + (b0 + m)) * 128 + j] = __float2half(h);
            }
        }
        __syncthreads();   // new h visible before next step
    }
}

// =====================================================================
// REC2: LSTM layer 2 recurrence + fused FC head. 128 CTAs x 8 rows.
// Thread = (unit j in 0..63, pair ph in 0..3 -> batch rows 2ph, 2ph+1).
// =====================================================================
__global__ void __launch_bounds__(256) rec2_kernel(
    const float* __restrict__ Whh,
    const float* __restrict__ fc1w, const float* __restrict__ fc1b,
    const float* __restrict__ fc2w, const float* __restrict__ fc2b,
    float* __restrict__ out)
{
    extern __shared__ char smc[];
    __half* sW = (__half*)smc;                 // [64][64][4] = 32 KiB
    float*  sH = (float*)(smc + 32768);        // [k=64][m=8] = 2 KiB
    const int tid = threadIdx.x;
    const int b0 = blockIdx.x * 8;

    for (int idx = tid; idx < 16384; idx += 256){
        int k = idx & 63;
        int j = (idx >> 6) & 63;
        int q = idx >> 12;
        sW[(k * 64 + j) * 4 + q] = __float2half(Whh[(q * 64 + j) * 64 + k]);
    }
    for (int i = tid; i < 512; i += 256) sH[i] = 0.f;
    __syncthreads();

    const int j = tid & 63, ph = tid >> 6;
    const int m0 = ph * 2;
    float cst[2] = {0.f, 0.f};
    const uint2* wp  = (const uint2*)sW + j;
    const float* hp0 = sH + m0;

    for (int t = 0; t < 512; t++){
        size_t base = ((size_t)t * 1024 + b0) * 256 + (size_t)j * 4;
        float4 xv0 = *(const float4*)(g_xw2 + base + (size_t)m0 * 256);
        float4 xv1 = *(const float4*)(g_xw2 + base + (size_t)(m0 + 1) * 256);

        ull acc[4] = {0ull, 0ull, 0ull, 0ull};
        #pragma unroll 4
        for (int k = 0; k < 64; k++){
            uint2 wraw = wp[k * 64];
            float2 w01 = __half22float2(*(const __half2*)&wraw.x);
            float2 w23 = __half22float2(*(const __half2*)&wraw.y);
            ull hv = *(const ull*)(hp0 + k * 8);
            acc[0] = ffma2(pack2(w01.x, w01.x), hv, acc[0]);
            acc[1] = ffma2(pack2(w01.y, w01.y), hv, acc[1]);
            acc[2] = ffma2(pack2(w23.x, w23.x), hv, acc[2]);
            acc[3] = ffma2(pack2(w23.y, w23.y), hv, acc[3]);
        }
        __syncthreads();

        float2 gi_ = unpack2(acc[0]);
        float2 gf_ = unpack2(acc[1]);
        float2 gg_ = unpack2(acc[2]);
        float2 go_ = unpack2(acc[3]);
        #pragma unroll
        for (int L = 0; L < 2; L++){
            const float4 x4 = L ? xv1 : xv0;
            float ai = (L ? gi_.y : gi_.x) + x4.x;
            float af = (L ? gf_.y : gf_.x) + x4.y;
            float ag = (L ? gg_.y : gg_.x) + x4.z;
            float ao = (L ? go_.y : go_.x) + x4.w;
            float iv = sigf(ai), fv = sigf(af), gv = tanh_f(ag), ov = sigf(ao);
            float cn = fv * cst[L] + iv * gv;
            cst[L] = cn;
            sH[j * 8 + m0 + L] = ov * tanh_f(cn);
        }
        __syncthreads();
    }

    // Fused FC head on final h2 (in sH[k][m]): warp w handles batch row m=w.
    const int m = tid >> 5, r = tid & 31;
    float s = fc1b[r];
    #pragma unroll 8
    for (int k = 0; k < 64; k++)
        s += sH[k * 8 + m] * fc1w[r * 64 + k];
    float z = fmaxf(s, 0.f) * fc2w[r];
    #pragma unroll
    for (int off = 16; off > 0; off >>= 1)
        z += __shfl_xor_sync(0xffffffffu, z, off);
    if (r == 0) out[b0 + m] = sigf(z + fc2b[0]);
}

// =====================================================================
extern "C" void kernel_launch(void* const* d_in, const int* in_sizes, int n_in,
                              void* d_out, int out_size)
{
    const float* X     = (const float*)d_in[0];
    const float* W1_ih = (const float*)d_in[1];
    const float* W1_hh = (const float*)d_in[2];
    const float* b1_ih = (const float*)d_in[3];
    const float* b1_hh = (const float*)d_in[4];
    const float* W2_ih = (const float*)d_in[5];
    const float* W2_hh = (const float*)d_in[6];
    const float* b2_ih = (const float*)d_in[7];
    const float* b2_hh = (const float*)d_in[8];
    const float* fc1w  = (const float*)d_in[9];
    const float* fc1b  = (const float*)d_in[10];
    const float* fc2w  = (const float*)d_in[11];
    const float* fc2b  = (const float*)d_in[12];
    float* out = (float*)d_out;

    const int g1_smem = (100 * 132 + 100 * 68) * 4;   // 80000 B
    const int g2_smem = (128 * 132 + 128 * 68) * 4;   // 102400 B
    const int r1_smem = 131072 + 4096;                // 135168 B
    const int r2_smem = 32768 + 2048;                 // 34816 B

    cudaFuncSetAttribute(gemm1_kernel, cudaFuncAttributeMaxDynamicSharedMemorySize, g1_smem);
    cudaFuncSetAttribute(gemm2_kernel, cudaFuncAttributeMaxDynamicSharedMemorySize, g2_smem);
    cudaFuncSetAttribute(rec1_kernel,  cudaFuncAttributeMaxDynamicSharedMemorySize, r1_smem);
    cudaFuncSetAttribute(rec2_kernel,  cudaFuncAttributeMaxDynamicSharedMemorySize, r2_smem);

    gemm1_kernel<<<dim3(8, 4096), 256, g1_smem>>>(X, W1_ih, b1_ih, b1_hh);
    rec1_kernel<<<128, 256, r1_smem>>>(W1_hh);
    gemm2_kernel<<<dim3(4, 4096), 256, g2_smem>>>(W2_ih, b2_ih, b2_hh);
    rec2_kernel<<<128, 256, r2_smem>>>(W2_hh, fc1w, fc1b, fc2w, fc2b, out);
}